// round 14
// baseline (speedup 1.0000x reference)
#include <cuda_runtime.h>
#include <cuda_bf16.h>
#include <math.h>
#include <stdint.h>

#define B_   4
#define S_   1024
#define H_   768
#define NH_  12
#define DH_  64
#define POS_ 2048

// softmax computed in base-2: scale = 0.125 * log2(e)
#define QSCALE 0.1803368801111204f
#define MSCALE (-94496.57f)   // -65500 * log2(e)

// ---------------- scratch (static device arrays; no allocations) ----------------
__device__ __nv_bfloat16 g_hidb[B_*S_*H_];
__device__ __nv_bfloat16 g_posb[B_*POS_*H_];
__device__ __nv_bfloat16 g_qwb [H_*H_];
__device__ __nv_bfloat16 g_kvwb[H_*H_];
__device__ __nv_bfloat16 g_rwgt[H_*H_];
__device__ __nv_bfloat16 g_wob [H_*H_];
__device__ __nv_bfloat16 g_maskb[B_*S_*S_];   // mask * MSCALE, bf16
__device__ __nv_bfloat16 g_qh [B_*S_*H_];
__device__ __nv_bfloat16 g_kvh[B_*S_*H_];
__device__ __nv_bfloat16 g_kr [B_*POS_*H_];
__device__ __nv_bfloat16 g_ctx[B_*S_*H_];

// ---------------- PTX helpers ---------------------------------------------------
__device__ __forceinline__ uint32_t sptr(const void* p) {
    return (uint32_t)__cvta_generic_to_shared(p);
}
__device__ __forceinline__ void ldsm4(uint32_t* r, uint32_t a) {
    asm volatile("ldmatrix.sync.aligned.m8n8.x4.shared.b16 {%0,%1,%2,%3},[%4];"
                 : "=r"(r[0]), "=r"(r[1]), "=r"(r[2]), "=r"(r[3]) : "r"(a));
}
__device__ __forceinline__ void ldsm4t(uint32_t* r, uint32_t a) {
    asm volatile("ldmatrix.sync.aligned.m8n8.x4.trans.shared.b16 {%0,%1,%2,%3},[%4];"
                 : "=r"(r[0]), "=r"(r[1]), "=r"(r[2]), "=r"(r[3]) : "r"(a));
}
__device__ __forceinline__ void mma16816(float* d, const uint32_t* a, const uint32_t* b) {
    asm volatile(
        "mma.sync.aligned.m16n8k16.row.col.f32.bf16.bf16.f32 "
        "{%0,%1,%2,%3},{%4,%5,%6,%7},{%8,%9},{%0,%1,%2,%3};"
        : "+f"(d[0]), "+f"(d[1]), "+f"(d[2]), "+f"(d[3])
        : "r"(a[0]), "r"(a[1]), "r"(a[2]), "r"(a[3]), "r"(b[0]), "r"(b[1]));
}
__device__ __forceinline__ void cpa16(uint32_t dst, const void* src) {
    asm volatile("cp.async.cg.shared.global [%0], [%1], 16;" :: "r"(dst), "l"(src));
}
__device__ __forceinline__ void cp_commit() {
    asm volatile("cp.async.commit_group;");
}
__device__ __forceinline__ void cp_wait0() {
    asm volatile("cp.async.wait_group 0;");
}
__device__ __forceinline__ uint32_t packbf(float a, float b) {
    __nv_bfloat162 h = __float22bfloat162_rn(make_float2(a, b));
    return *(uint32_t*)&h;
}
__device__ __forceinline__ float ex2f(float x) {
    float r;
    asm("ex2.approx.ftz.f32 %0, %1;" : "=f"(r) : "f"(x));
    return r;
}

// ---------------- fp32 -> bf16 conversion (all tensors + mask) ------------------
__global__ void convert_all(const float* __restrict__ h, const float* __restrict__ p,
                            const float* __restrict__ qw, const float* __restrict__ kvw,
                            const float* __restrict__ rw, const float* __restrict__ wo,
                            const float* __restrict__ mk)
{
    const int N1 = 786432;            // hidden  (float4 units)
    const int N2 = N1 + 1572864;      // pos_emb
    const int N3 = N2 + 147456;       // qw
    const int N4 = N3 + 147456;       // kvw
    const int N5 = N4 + 147456;       // rw
    const int N6 = N5 + 147456;       // wo
    const int N7 = N6 + 1048576;      // mask (premultiplied, base-2 scale)
    for (int i = blockIdx.x * blockDim.x + threadIdx.x; i < N7;
         i += gridDim.x * blockDim.x) {
        const float* src; __nv_bfloat16* dst; int li; float sc = 1.f;
        if      (i < N1) { src = h;   dst = g_hidb; li = i; }
        else if (i < N2) { src = p;   dst = g_posb; li = i - N1; }
        else if (i < N3) { src = qw;  dst = g_qwb;  li = i - N2; }
        else if (i < N4) { src = kvw; dst = g_kvwb; li = i - N3; }
        else if (i < N5) { src = rw;  dst = g_rwgt; li = i - N4; }
        else if (i < N6) { src = wo;  dst = g_wob;  li = i - N5; }
        else             { src = mk;  dst = g_maskb; li = i - N6; sc = MSCALE; }
        float4 v = ((const float4*)src)[li];
        uint2 u;
        u.x = packbf(v.x * sc, v.y * sc);
        u.y = packbf(v.z * sc, v.w * sc);
        ((uint2*)dst)[li] = u;
    }
}

// ---------------- bf16 GEMM, 64x128x64 tiles, 2-stage, occ 3 --------------------
#define QSTG 13312
#define NKI  12         // 768 / 64

__device__ __forceinline__ void q_load(int tid, const __nv_bfloat16* A,
    const __nv_bfloat16* W, int m0, int c0, int k0, uint32_t sbase)
{
#pragma unroll
    for (int it = 0; it < 2; it++) {
        const int id = tid + it * 256;
        const int r = id >> 3, c = (id & 7) * 8;
        cpa16(sbase + (r * 72 + c) * 2, &A[(size_t)(m0 + r) * H_ + k0 + c]);
    }
#pragma unroll
    for (int it = 0; it < 4; it++) {
        const int id = tid + it * 256;
        const int r = id >> 4, c = (id & 15) * 8;
        cpa16(sbase + (4608 + r * 136 + c) * 2, &W[(size_t)(k0 + r) * H_ + c0 + c]);
    }
    cp_commit();
}

template<bool EPI>
__device__ __forceinline__ void gemm64_body(
    const __nv_bfloat16* __restrict__ A, const __nv_bfloat16* __restrict__ W,
    int m0, int c0, __nv_bfloat16* __restrict__ outH, float* __restrict__ outF,
    const float* __restrict__ bias, const float* __restrict__ resid)
{
    extern __shared__ __align__(16) __nv_bfloat16 gsm[];
    const int tid = threadIdx.x;
    const int wid = tid >> 5, lane = tid & 31;
    const int wm = wid & 1, wn = wid >> 1;
    const int g = lane >> 2, tig = lane & 3;

    const uint32_t s0 = sptr(gsm);
    q_load(tid, A, W, m0, c0, 0, s0);

    float acc[2][4][4];
#pragma unroll
    for (int mi = 0; mi < 2; mi++)
#pragma unroll
        for (int nt = 0; nt < 4; nt++)
#pragma unroll
            for (int e = 0; e < 4; e++) acc[mi][nt][e] = 0.f;

    const uint32_t a_off = ((wm * 32 + (lane & 15)) * 72 + (lane >> 4) * 8) << 1;
    const uint32_t b_off = (4608 + ((lane & 15)) * 136 + wn * 32 + (lane >> 4) * 8) << 1;

    for (int ki = 0; ki < NKI; ki++) {
        cp_wait0();
        __syncthreads();
        if (ki + 1 < NKI)
            q_load(tid, A, W, m0, c0, (ki + 1) * 64,
                   s0 + (((ki + 1) & 1) * QSTG << 1));
        const uint32_t sb = s0 + ((ki & 1) * QSTG << 1);
        const uint32_t a_base = sb + a_off, b_base = sb + b_off;
#pragma unroll
        for (int kc = 0; kc < 4; kc++) {
            uint32_t af[2][4], bv[2][4];
#pragma unroll
            for (int mi = 0; mi < 2; mi++)
                ldsm4(af[mi], a_base + ((mi * 16 * 72 + kc * 16) << 1));
#pragma unroll
            for (int nn = 0; nn < 2; nn++)
                ldsm4t(bv[nn], b_base + ((kc * 16 * 136 + nn * 16) << 1));
#pragma unroll
            for (int mi = 0; mi < 2; mi++)
#pragma unroll
                for (int nn = 0; nn < 2; nn++) {
                    mma16816(acc[mi][2 * nn + 0], af[mi], &bv[nn][0]);
                    mma16816(acc[mi][2 * nn + 1], af[mi], &bv[nn][2]);
                }
        }
        __syncthreads();
    }

#pragma unroll
    for (int mi = 0; mi < 2; mi++) {
#pragma unroll
        for (int nt = 0; nt < 4; nt++) {
            const int col = c0 + wn * 32 + nt * 8 + 2 * tig;
#pragma unroll
            for (int half = 0; half < 2; half++) {
                const int r = m0 + wm * 32 + mi * 16 + g + half * 8;
                float v0 = acc[mi][nt][half * 2 + 0];
                float v1 = acc[mi][nt][half * 2 + 1];
                if (EPI) {
                    float x0 = v0 + bias[col]     + resid[(size_t)r * H_ + col];
                    float x1 = v1 + bias[col + 1] + resid[(size_t)r * H_ + col + 1];
                    v0 = 0.5f * x0 * (1.f + erff(x0 * 0.70710678118654752f));
                    v1 = 0.5f * x1 * (1.f + erff(x1 * 0.70710678118654752f));
                    float* cp = &outF[(size_t)r * H_ + col];
                    cp[0] = v0; cp[1] = v1;
                } else {
                    *(uint32_t*)&outH[(size_t)r * H_ + col] = packbf(v0, v1);
                }
            }
        }
    }
}

// All three projections in ONE launch: 1536 blocks of 64x128.
__global__ __launch_bounds__(256, 3) void proj_all()
{
    const int bid = blockIdx.x;
    const __nv_bfloat16 *A, *W;
    __nv_bfloat16* C;
    int m0, c0;
    if (bid < 768) {
        const int x = bid % 12, y = bid / 12;
        m0 = y * 64;
        A = g_hidb;
        if (x < 6) { W = g_qwb;  C = g_qh;  c0 = x * 128; }
        else       { W = g_kvwb; C = g_kvh; c0 = (x - 6) * 128; }
    } else {
        const int t = bid - 768;
        const int x = t % 6, y = t / 6;
        m0 = y * 64; c0 = x * 128;
        A = g_posb; W = g_rwgt; C = g_kr;
    }
    gemm64_body<false>(A, W, m0, c0, C, nullptr, nullptr, nullptr);
}

// Output projection + bias + residual + exact GELU. 384 blocks of 64x128.
__global__ __launch_bounds__(256, 3) void gemm_epi(
    float* __restrict__ out, const float* __restrict__ bias,
    const float* __restrict__ resid)
{
    const int x = blockIdx.x % 6, y = blockIdx.x / 6;
    gemm64_body<true>(g_ctx, g_wob, y * 64, x * 128, nullptr, out, bias, resid);
}

// ---------------- FA2-style flash attention, STATIC base-2 softmax --------------
// Change vs best (234us) kernel: per-jt phase order is now G -> S -> softmax -> PV
// (G no longer overlaps acc_s's live range), and the Qr fragments (afr) are
// recomputed per jt inside the G phase instead of held across the key loop.
// Only dpk0/dpk1 (8 regs) stay hoisted. Math identical.
#define FLH 72
#define FGS 68
__global__ __launch_bounds__(256, 2) void flash_mma(
    const float* __restrict__ rwbias, const float* __restrict__ rrbias)
{
    extern __shared__ __align__(16) char smraw[];
    __nv_bfloat16* qw_s = (__nv_bfloat16*)smraw;        // 128 x 72
    __nv_bfloat16* kv_s = qw_s + 128 * FLH;             // 2 x 64 x 72
    __nv_bfloat16* kr_s = kv_s + 2 * 64 * FLH;          // ring: 256 x 72
    float* gsh = (float*)(kr_s + 256 * FLH);            // 8 x 16 x 68
    float* bw  = gsh + 8 * 16 * FGS;                    // 64
    float* br  = bw + 64;                               // 64

    const int b = blockIdx.z, n = blockIdx.y;
    const int i0 = blockIdx.x * 128;
    const int tid = threadIdx.x;
    const int w = tid >> 5, lane = tid & 31;
    const int g = lane >> 2, tig = lane & 3;
    const int pb0 = 897 - i0;

    if (tid < 64)       bw[tid]      = rwbias[n * DH_ + tid];
    else if (tid < 128) br[tid - 64] = rrbias[n * DH_ + tid - 64];
    __syncthreads();

    const uint32_t kvsm = sptr(kv_s), krsm = sptr(kr_s);

    // ---- initial async loads: kv tile 0 + full 191-row kr window ----
#pragma unroll
    for (int it = 0; it < 2; it++) {
        const int id = tid + it * 256;
        const int r = id >> 3, c = (id & 7) * 8;
        cpa16(kvsm + (r * FLH + c) * 2,
              &g_kvh[(((size_t)b * S_ + r) * NH_ + n) * DH_ + c]);
    }
#pragma unroll
    for (int it = 0; it < 6; it++) {
        const int id = tid + it * 256;
        const int r = id >> 3, c = (id & 7) * 8;
        if (r < 191) {
            const int rowabs = pb0 + r;
            cpa16(krsm + ((rowabs & 255) * FLH + c) * 2,
                  &g_kr[(((size_t)b * POS_ + rowabs) * NH_ + n) * DH_ + c]);
        }
    }
    cp_commit();

    // ---- build biased+scaled Q tile: (q + r_w_bias) * QSCALE ----
#pragma unroll
    for (int it = 0; it < 4; it++) {
        const int id = tid + it * 256;
        const int r = id >> 3, c = (id & 7) * 8;
        uint4 v = *(const uint4*)&g_qh[(((size_t)b * S_ + i0 + r) * NH_ + n) * DH_ + c];
        __nv_bfloat162* hp = (__nv_bfloat162*)&v;
        uint4 ow;
        uint32_t* wp = (uint32_t*)&ow;
#pragma unroll
        for (int k = 0; k < 4; k++) {
            float2 f = __bfloat1622float2(hp[k]);
            wp[k] = packbf((f.x + bw[c + 2 * k]) * QSCALE,
                           (f.y + bw[c + 2 * k + 1]) * QSCALE);
        }
        *(uint4*)&qw_s[r * FLH + c] = ow;
    }

    // ---- delta fragments: packed bf16 (br - bw)*QSCALE (only these hoisted) ----
    uint32_t dpk0[4], dpk1[4];
#pragma unroll
    for (int kc = 0; kc < 4; kc++) {
        const int kA = 16 * kc + 2 * tig;
        dpk0[kc] = packbf((br[kA] - bw[kA]) * QSCALE, (br[kA + 1] - bw[kA + 1]) * QSCALE);
        dpk1[kc] = packbf((br[kA + 8] - bw[kA + 8]) * QSCALE, (br[kA + 9] - bw[kA + 9]) * QSCALE);
    }
    __syncthreads();

    const uint32_t qwa = sptr(qw_s) + (((16 * w + (lane & 15)) * FLH + (lane >> 4) * 8) << 1);
    const uint32_t kvn = kvsm + (((((lane >> 4) * 8 + (lane & 7)) * FLH) + ((lane >> 3) & 1) * 8) << 1);
    const uint32_t kvt = kvsm + ((((lane & 15)) * FLH + (lane >> 4) * 8) << 1);
    const int laneRow = (lane >> 4) * 8 + (lane & 7);
    const int khalf   = ((lane >> 3) & 1) * 8;

    float l0v = 0.f, l1v = 0.f;
    float acc_o[8][4];
#pragma unroll
    for (int nt = 0; nt < 8; nt++)
#pragma unroll
        for (int e = 0; e < 4; e++) acc_o[nt][e] = 0.f;

    const int nt0 = 14 - 2 * w;
    float* gw = gsh + w * 16 * FGS;
    const int gi0 = i0 + 16 * w + g;
    const __nv_bfloat16* mrow0 = g_maskb + ((size_t)b * S_ + gi0) * S_;
    const __nv_bfloat16* mrow1 = mrow0 + 8 * S_;

    for (int jt = 0; jt < 16; jt++) {
        cp_wait0();
        __syncthreads();
        if (jt < 15) {
            const int j1 = (jt + 1) * 64;
            const uint32_t kvb = kvsm + (((jt + 1) & 1) * 64 * FLH << 1);
#pragma unroll
            for (int it = 0; it < 2; it++) {
                const int id = tid + it * 256;
                const int r = id >> 3, c = (id & 7) * 8;
                cpa16(kvb + (r * FLH + c) * 2,
                      &g_kvh[(((size_t)b * S_ + j1 + r) * NH_ + n) * DH_ + c]);
            }
            const int nb = pb0 + 64 * jt + 191;
#pragma unroll
            for (int it = 0; it < 2; it++) {
                const int id = tid + it * 256;
                const int r = id >> 3, c = (id & 7) * 8;
                const int rowabs = nb + r;
                cpa16(krsm + ((rowabs & 255) * FLH + c) * 2,
                      &g_kr[(((size_t)b * POS_ + rowabs) * NH_ + n) * DH_ + c]);
            }
            cp_commit();
        }
        const uint32_t kvo = ((jt & 1) * 64 * FLH) << 1;
        const int j0 = jt * 64;
        const int rowj = pb0 + 64 * jt + laneRow;

        // ---- PHASE 1: banded G = Qr @ KR_ring^T (afr recomputed here) ----
        {
            uint32_t afr[4][4];
#pragma unroll
            for (int kc = 0; kc < 4; kc++) {
                uint32_t aq[4];
                ldsm4(aq, qwa + kc * 32);
                __nv_bfloat162 r0 = __hadd2(*(__nv_bfloat162*)&aq[0], *(__nv_bfloat162*)&dpk0[kc]);
                __nv_bfloat162 r1 = __hadd2(*(__nv_bfloat162*)&aq[1], *(__nv_bfloat162*)&dpk0[kc]);
                __nv_bfloat162 r2 = __hadd2(*(__nv_bfloat162*)&aq[2], *(__nv_bfloat162*)&dpk1[kc]);
                __nv_bfloat162 r3 = __hadd2(*(__nv_bfloat162*)&aq[3], *(__nv_bfloat162*)&dpk1[kc]);
                afr[kc][0] = *(uint32_t*)&r0;
                afr[kc][1] = *(uint32_t*)&r1;
                afr[kc][2] = *(uint32_t*)&r2;
                afr[kc][3] = *(uint32_t*)&r3;
            }
            uint32_t gbf[2][4];
            {
                const int tr0 = nt0 * 8;
                ldsm4(gbf[0], krsm + ((((rowj + tr0) & 255) * FLH + khalf) << 1));
            }
#pragma unroll
            for (int np = 0; np < 5; np++) {
                const int tr = (nt0 + 2 * np) * 8;
                float ga[4] = {0.f, 0.f, 0.f, 0.f};
                float gb[4] = {0.f, 0.f, 0.f, 0.f};
#pragma unroll
                for (int kc = 0; kc < 4; kc++) {
                    const int it = np * 4 + kc;
                    const int cur = it & 1;
                    if (it < 19) {
                        const int itn = it + 1;
                        const int npn = itn >> 2, kn = itn & 3;
                        const int trn = (nt0 + 2 * npn) * 8;
                        ldsm4(gbf[cur ^ 1],
                              krsm + ((((rowj + trn) & 255) * FLH + khalf) << 1) + kn * 32);
                    }
                    mma16816(ga, afr[kc], &gbf[cur][0]);
                    mma16816(gb, afr[kc], &gbf[cur][2]);
                }
                const int base = tr + 2 * tig + 16 * w - 127;
                const int cA = base + g;
                const int cB = cA + 8;
                if ((unsigned)cA < 64u)        gw[g * FGS + cA]             = ga[0];
                if ((unsigned)(cA + 1) < 64u)  gw[g * FGS + cA + 1]         = ga[1];
                if ((unsigned)cB < 64u)        gw[(g + 8) * FGS + cB]       = ga[2];
                if ((unsigned)(cB + 1) < 64u)  gw[(g + 8) * FGS + cB + 1]   = ga[3];
                const int cA2 = cA + 8;
                const int cB2 = cB + 8;
                if ((unsigned)cA2 < 64u)       gw[g * FGS + cA2]            = gb[0];
                if ((unsigned)(cA2 + 1) < 64u) gw[g * FGS + cA2 + 1]        = gb[1];
                if ((unsigned)cB2 < 64u)       gw[(g + 8) * FGS + cB2]      = gb[2];
                if ((unsigned)(cB2 + 1) < 64u) gw[(g + 8) * FGS + cB2 + 1]  = gb[3];
            }
        }
        __syncwarp();

        // ---- PHASE 2: S = Qw @ KV^T (af reloaded per kc) ----
        float acc_s[8][4];
#pragma unroll
        for (int nt = 0; nt < 8; nt++)
#pragma unroll
            for (int e = 0; e < 4; e++) acc_s[nt][e] = 0.f;
        {
            uint32_t sbf[2][4];
            ldsm4(sbf[0], kvn + kvo);
#pragma unroll
            for (int kc = 0; kc < 4; kc++) {
                uint32_t afk[4];
                ldsm4(afk, qwa + kc * 32);
#pragma unroll
                for (int nn = 0; nn < 4; nn++) {
                    const int it = kc * 4 + nn;
                    const int cur = it & 1;
                    if (it < 15) {
                        const int itn = it + 1;
                        const int kn = itn >> 2, nnn = itn & 3;
                        ldsm4(sbf[cur ^ 1], kvn + kvo + ((nnn * 16 * FLH + kn * 16) << 1));
                    }
                    mma16816(acc_s[2 * nn + 0], afk, &sbf[cur][0]);
                    mma16816(acc_s[2 * nn + 1], afk, &sbf[cur][2]);
                }
            }
        }

        // ---- PHASE 3: static base-2 softmax: p = ex2(s + g + mask) ----
        uint32_t pa[4][4];
#pragma unroll
        for (int nt = 0; nt < 8; nt++) {
            const int colb = nt * 8 + 2 * tig;
            const float2 mv0 = __bfloat1622float2(
                *(const __nv_bfloat162*)&mrow0[j0 + colb]);
            const float2 mv1 = __bfloat1622float2(
                *(const __nv_bfloat162*)&mrow1[j0 + colb]);
            const float2 gv0 = *(const float2*)&gw[g * FGS + colb];
            const float2 gv1 = *(const float2*)&gw[(g + 8) * FGS + colb];
            const float p0 = ex2f(acc_s[nt][0] + gv0.x + mv0.x);
            const float p1 = ex2f(acc_s[nt][1] + gv0.y + mv0.y);
            const float p2 = ex2f(acc_s[nt][2] + gv1.x + mv1.x);
            const float p3 = ex2f(acc_s[nt][3] + gv1.y + mv1.y);
            l0v += p0 + p1;
            l1v += p2 + p3;
            pa[nt >> 1][(nt & 1) * 2 + 0] = packbf(p0, p1);
            pa[nt >> 1][(nt & 1) * 2 + 1] = packbf(p2, p3);
        }

        // ---- PHASE 4: O += P @ V, pipelined B fragments ----
        {
            uint32_t obf[2][4];
            ldsm4t(obf[0], kvt + kvo);
#pragma unroll
            for (int kc = 0; kc < 4; kc++) {
#pragma unroll
                for (int nn = 0; nn < 4; nn++) {
                    const int it = kc * 4 + nn;
                    const int cur = it & 1;
                    if (it < 15) {
                        const int itn = it + 1;
                        const int kn = itn >> 2, nnn = itn & 3;
                        ldsm4t(obf[cur ^ 1], kvt + kvo + ((kn * 16 * FLH + nnn * 16) << 1));
                    }
                    mma16816(acc_o[2 * nn + 0], pa[kc], &obf[cur][0]);
                    mma16816(acc_o[2 * nn + 1], pa[kc], &obf[cur][2]);
                }
            }
        }
    }

    // ---- one final l reduction across the quad, then normalize and store ----
    l0v += __shfl_xor_sync(0xffffffffu, l0v, 1);
    l0v += __shfl_xor_sync(0xffffffffu, l0v, 2);
    l1v += __shfl_xor_sync(0xffffffffu, l1v, 1);
    l1v += __shfl_xor_sync(0xffffffffu, l1v, 2);
    const float inv0 = 1.f / l0v, inv1 = 1.f / l1v;
    const size_t b0 = (((size_t)b * S_ + i0 + 16 * w + g) * NH_ + n) * (size_t)DH_;
    const size_t b1 = b0 + 8 * (size_t)NH_ * DH_;
#pragma unroll
    for (int nt = 0; nt < 8; nt++) {
        const int c = nt * 8 + 2 * tig;
        *(uint32_t*)&g_ctx[b0 + c] = packbf(acc_o[nt][0] * inv0, acc_o[nt][1] * inv0);
        *(uint32_t*)&g_ctx[b1 + c] = packbf(acc_o[nt][2] * inv1, acc_o[nt][3] * inv1);
    }
}

// -------------------------------- launch ---------------------------------------
extern "C" void kernel_launch(void* const* d_in, const int* in_sizes, int n_in,
                              void* d_out, int out_size)
{
    const float* hidden   = (const float*)d_in[0];
    const float* pos_emb  = (const float*)d_in[1];
    const float* mask     = (const float*)d_in[2];
    const float* qw       = (const float*)d_in[3];
    const float* kvw      = (const float*)d_in[4];
    const float* rw       = (const float*)d_in[5];
    const float* r_r_bias = (const float*)d_in[6];
    const float* r_w_bias = (const float*)d_in[7];
    const float* w_out    = (const float*)d_in[8];
    const float* b_out    = (const float*)d_in[9];
    float* out = (float*)d_out;

    const int gemm_smem  = 2 * QSTG * 2;                        // 53248 B
    const int flash_smem = (128 * FLH + 2 * 64 * FLH + 256 * FLH) * 2
                           + (8 * 16 * FGS + 128) * 4;          // 109056 B
    cudaFuncSetAttribute(proj_all,
                         cudaFuncAttributeMaxDynamicSharedMemorySize, gemm_smem);
    cudaFuncSetAttribute(gemm_epi,
                         cudaFuncAttributeMaxDynamicSharedMemorySize, gemm_smem);
    cudaFuncSetAttribute(flash_mma,
                         cudaFuncAttributeMaxDynamicSharedMemorySize, flash_smem);

    // fp32 -> bf16 conversion (inputs, weights, premultiplied mask)
    convert_all<<<2048, 256>>>(hidden, pos_emb, qw, kvw, rw, w_out, mask);

    // q + kv + r projections in a single launch (1536 CTAs of 64x128, occ 3)
    proj_all<<<1536, 256, gemm_smem>>>();

    // fused attention (static base-2 softmax, G-first phase order)
    flash_mma<<<dim3(S_/128, NH_, B_), 256, flash_smem>>>(r_w_bias, r_r_bias);

    // output projection + bias + residual + exact GELU (384 CTAs, occ 3)
    gemm_epi<<<384, 256, gemm_smem>>>(out, b_out, hidden);
}

// round 15
// speedup vs baseline: 1.5583x; 1.5583x over previous
#include <cuda_runtime.h>
#include <cuda_bf16.h>
#include <math.h>
#include <stdint.h>

#define B_   4
#define S_   1024
#define H_   768
#define NH_  12
#define DH_  64
#define POS_ 2048

// softmax computed in base-2: scale = 0.125 * log2(e)
#define QSCALE 0.1803368801111204f
#define MSCALE (-94496.57f)   // -65500 * log2(e)

// ---------------- scratch (static device arrays; no allocations) ----------------
__device__ __nv_bfloat16 g_hidb[B_*S_*H_];
__device__ __nv_bfloat16 g_posb[B_*POS_*H_];
__device__ __nv_bfloat16 g_qwb [H_*H_];
__device__ __nv_bfloat16 g_kvwb[H_*H_];
__device__ __nv_bfloat16 g_rwgt[H_*H_];
__device__ __nv_bfloat16 g_wob [H_*H_];
__device__ __nv_bfloat16 g_maskb[B_*S_*S_];   // mask * MSCALE, bf16
__device__ __nv_bfloat16 g_qh [B_*S_*H_];
__device__ __nv_bfloat16 g_kvh[B_*S_*H_];
__device__ __nv_bfloat16 g_kr [B_*POS_*H_];
__device__ __nv_bfloat16 g_ctx[B_*S_*H_];

// ---------------- PTX helpers ---------------------------------------------------
__device__ __forceinline__ uint32_t sptr(const void* p) {
    return (uint32_t)__cvta_generic_to_shared(p);
}
__device__ __forceinline__ void ldsm4(uint32_t* r, uint32_t a) {
    asm volatile("ldmatrix.sync.aligned.m8n8.x4.shared.b16 {%0,%1,%2,%3},[%4];"
                 : "=r"(r[0]), "=r"(r[1]), "=r"(r[2]), "=r"(r[3]) : "r"(a));
}
__device__ __forceinline__ void ldsm4t(uint32_t* r, uint32_t a) {
    asm volatile("ldmatrix.sync.aligned.m8n8.x4.trans.shared.b16 {%0,%1,%2,%3},[%4];"
                 : "=r"(r[0]), "=r"(r[1]), "=r"(r[2]), "=r"(r[3]) : "r"(a));
}
__device__ __forceinline__ void mma16816(float* d, const uint32_t* a, const uint32_t* b) {
    asm volatile(
        "mma.sync.aligned.m16n8k16.row.col.f32.bf16.bf16.f32 "
        "{%0,%1,%2,%3},{%4,%5,%6,%7},{%8,%9},{%0,%1,%2,%3};"
        : "+f"(d[0]), "+f"(d[1]), "+f"(d[2]), "+f"(d[3])
        : "r"(a[0]), "r"(a[1]), "r"(a[2]), "r"(a[3]), "r"(b[0]), "r"(b[1]));
}
__device__ __forceinline__ void cpa16(uint32_t dst, const void* src) {
    asm volatile("cp.async.cg.shared.global [%0], [%1], 16;" :: "r"(dst), "l"(src));
}
__device__ __forceinline__ void cp_commit() {
    asm volatile("cp.async.commit_group;");
}
__device__ __forceinline__ void cp_wait0() {
    asm volatile("cp.async.wait_group 0;");
}
__device__ __forceinline__ uint32_t packbf(float a, float b) {
    __nv_bfloat162 h = __float22bfloat162_rn(make_float2(a, b));
    return *(uint32_t*)&h;
}
__device__ __forceinline__ float ex2f(float x) {
    float r;
    asm("ex2.approx.ftz.f32 %0, %1;" : "=f"(r) : "f"(x));
    return r;
}

// ---------------- fp32 -> bf16 conversion (all tensors + mask) ------------------
__global__ void convert_all(const float* __restrict__ h, const float* __restrict__ p,
                            const float* __restrict__ qw, const float* __restrict__ kvw,
                            const float* __restrict__ rw, const float* __restrict__ wo,
                            const float* __restrict__ mk)
{
    const int N1 = 786432;            // hidden  (float4 units)
    const int N2 = N1 + 1572864;      // pos_emb
    const int N3 = N2 + 147456;       // qw
    const int N4 = N3 + 147456;       // kvw
    const int N5 = N4 + 147456;       // rw
    const int N6 = N5 + 147456;       // wo
    const int N7 = N6 + 1048576;      // mask (premultiplied, base-2 scale)
    for (int i = blockIdx.x * blockDim.x + threadIdx.x; i < N7;
         i += gridDim.x * blockDim.x) {
        const float* src; __nv_bfloat16* dst; int li; float sc = 1.f;
        if      (i < N1) { src = h;   dst = g_hidb; li = i; }
        else if (i < N2) { src = p;   dst = g_posb; li = i - N1; }
        else if (i < N3) { src = qw;  dst = g_qwb;  li = i - N2; }
        else if (i < N4) { src = kvw; dst = g_kvwb; li = i - N3; }
        else if (i < N5) { src = rw;  dst = g_rwgt; li = i - N4; }
        else if (i < N6) { src = wo;  dst = g_wob;  li = i - N5; }
        else             { src = mk;  dst = g_maskb; li = i - N6; sc = MSCALE; }
        float4 v = ((const float4*)src)[li];
        uint2 u;
        u.x = packbf(v.x * sc, v.y * sc);
        u.y = packbf(v.z * sc, v.w * sc);
        ((uint2*)dst)[li] = u;
    }
}

// ---------------- bf16 GEMM, 64x128x64 tiles, 2-stage, occ 3 --------------------
#define QSTG 13312
#define NKI  12         // 768 / 64

__device__ __forceinline__ void q_load(int tid, const __nv_bfloat16* A,
    const __nv_bfloat16* W, int m0, int c0, int k0, uint32_t sbase)
{
#pragma unroll
    for (int it = 0; it < 2; it++) {
        const int id = tid + it * 256;
        const int r = id >> 3, c = (id & 7) * 8;
        cpa16(sbase + (r * 72 + c) * 2, &A[(size_t)(m0 + r) * H_ + k0 + c]);
    }
#pragma unroll
    for (int it = 0; it < 4; it++) {
        const int id = tid + it * 256;
        const int r = id >> 4, c = (id & 15) * 8;
        cpa16(sbase + (4608 + r * 136 + c) * 2, &W[(size_t)(k0 + r) * H_ + c0 + c]);
    }
    cp_commit();
}

template<bool EPI>
__device__ __forceinline__ void gemm64_body(
    const __nv_bfloat16* __restrict__ A, const __nv_bfloat16* __restrict__ W,
    int m0, int c0, __nv_bfloat16* __restrict__ outH, float* __restrict__ outF,
    const float* __restrict__ bias, const float* __restrict__ resid)
{
    extern __shared__ __align__(16) __nv_bfloat16 gsm[];
    const int tid = threadIdx.x;
    const int wid = tid >> 5, lane = tid & 31;
    const int wm = wid & 1, wn = wid >> 1;
    const int g = lane >> 2, tig = lane & 3;

    const uint32_t s0 = sptr(gsm);
    q_load(tid, A, W, m0, c0, 0, s0);

    float acc[2][4][4];
#pragma unroll
    for (int mi = 0; mi < 2; mi++)
#pragma unroll
        for (int nt = 0; nt < 4; nt++)
#pragma unroll
            for (int e = 0; e < 4; e++) acc[mi][nt][e] = 0.f;

    const uint32_t a_off = ((wm * 32 + (lane & 15)) * 72 + (lane >> 4) * 8) << 1;
    const uint32_t b_off = (4608 + ((lane & 15)) * 136 + wn * 32 + (lane >> 4) * 8) << 1;

    for (int ki = 0; ki < NKI; ki++) {
        cp_wait0();
        __syncthreads();
        if (ki + 1 < NKI)
            q_load(tid, A, W, m0, c0, (ki + 1) * 64,
                   s0 + (((ki + 1) & 1) * QSTG << 1));
        const uint32_t sb = s0 + ((ki & 1) * QSTG << 1);
        const uint32_t a_base = sb + a_off, b_base = sb + b_off;
#pragma unroll
        for (int kc = 0; kc < 4; kc++) {
            uint32_t af[2][4], bv[2][4];
#pragma unroll
            for (int mi = 0; mi < 2; mi++)
                ldsm4(af[mi], a_base + ((mi * 16 * 72 + kc * 16) << 1));
#pragma unroll
            for (int nn = 0; nn < 2; nn++)
                ldsm4t(bv[nn], b_base + ((kc * 16 * 136 + nn * 16) << 1));
#pragma unroll
            for (int mi = 0; mi < 2; mi++)
#pragma unroll
                for (int nn = 0; nn < 2; nn++) {
                    mma16816(acc[mi][2 * nn + 0], af[mi], &bv[nn][0]);
                    mma16816(acc[mi][2 * nn + 1], af[mi], &bv[nn][2]);
                }
        }
        __syncthreads();
    }

#pragma unroll
    for (int mi = 0; mi < 2; mi++) {
#pragma unroll
        for (int nt = 0; nt < 4; nt++) {
            const int col = c0 + wn * 32 + nt * 8 + 2 * tig;
#pragma unroll
            for (int half = 0; half < 2; half++) {
                const int r = m0 + wm * 32 + mi * 16 + g + half * 8;
                float v0 = acc[mi][nt][half * 2 + 0];
                float v1 = acc[mi][nt][half * 2 + 1];
                if (EPI) {
                    const float2 rv = *(const float2*)&resid[(size_t)r * H_ + col];
                    float x0 = v0 + bias[col]     + rv.x;
                    float x1 = v1 + bias[col + 1] + rv.y;
                    v0 = 0.5f * x0 * (1.f + erff(x0 * 0.70710678118654752f));
                    v1 = 0.5f * x1 * (1.f + erff(x1 * 0.70710678118654752f));
                    *(float2*)&outF[(size_t)r * H_ + col] = make_float2(v0, v1);
                } else {
                    *(uint32_t*)&outH[(size_t)r * H_ + col] = packbf(v0, v1);
                }
            }
        }
    }
}

// All three projections in ONE launch: 1536 blocks of 64x128.
__global__ __launch_bounds__(256, 3) void proj_all()
{
    const int bid = blockIdx.x;
    const __nv_bfloat16 *A, *W;
    __nv_bfloat16* C;
    int m0, c0;
    if (bid < 768) {
        const int x = bid % 12, y = bid / 12;
        m0 = y * 64;
        A = g_hidb;
        if (x < 6) { W = g_qwb;  C = g_qh;  c0 = x * 128; }
        else       { W = g_kvwb; C = g_kvh; c0 = (x - 6) * 128; }
    } else {
        const int t = bid - 768;
        const int x = t % 6, y = t / 6;
        m0 = y * 64; c0 = x * 128;
        A = g_posb; W = g_rwgt; C = g_kr;
    }
    gemm64_body<false>(A, W, m0, c0, C, nullptr, nullptr, nullptr);
}

// Output projection + bias + residual + exact GELU. 384 blocks of 64x128.
__global__ __launch_bounds__(256, 3) void gemm_epi(
    float* __restrict__ out, const float* __restrict__ bias,
    const float* __restrict__ resid)
{
    const int x = blockIdx.x % 6, y = blockIdx.x / 6;
    gemm64_body<true>(g_ctx, g_wob, y * 64, x * 128, nullptr, out, bias, resid);
}

// ---------------- FA2-style flash attention, STATIC base-2 softmax --------------
// R13 configuration (measured best): afr hoisted once before the key loop;
// Qw fragments reloaded per kc in the S loop; order S -> G -> softmax -> PV.
#define FLH 72
#define FGS 68
__global__ __launch_bounds__(256, 2) void flash_mma(
    const float* __restrict__ rwbias, const float* __restrict__ rrbias)
{
    extern __shared__ __align__(16) char smraw[];
    __nv_bfloat16* qw_s = (__nv_bfloat16*)smraw;        // 128 x 72
    __nv_bfloat16* kv_s = qw_s + 128 * FLH;             // 2 x 64 x 72
    __nv_bfloat16* kr_s = kv_s + 2 * 64 * FLH;          // ring: 256 x 72
    float* gsh = (float*)(kr_s + 256 * FLH);            // 8 x 16 x 68
    float* bw  = gsh + 8 * 16 * FGS;                    // 64
    float* br  = bw + 64;                               // 64

    const int b = blockIdx.z, n = blockIdx.y;
    const int i0 = blockIdx.x * 128;
    const int tid = threadIdx.x;
    const int w = tid >> 5, lane = tid & 31;
    const int g = lane >> 2, tig = lane & 3;
    const int pb0 = 897 - i0;

    if (tid < 64)       bw[tid]      = rwbias[n * DH_ + tid];
    else if (tid < 128) br[tid - 64] = rrbias[n * DH_ + tid - 64];
    __syncthreads();

    const uint32_t kvsm = sptr(kv_s), krsm = sptr(kr_s);

    // ---- initial async loads: kv tile 0 + full 191-row kr window ----
#pragma unroll
    for (int it = 0; it < 2; it++) {
        const int id = tid + it * 256;
        const int r = id >> 3, c = (id & 7) * 8;
        cpa16(kvsm + (r * FLH + c) * 2,
              &g_kvh[(((size_t)b * S_ + r) * NH_ + n) * DH_ + c]);
    }
#pragma unroll
    for (int it = 0; it < 6; it++) {
        const int id = tid + it * 256;
        const int r = id >> 3, c = (id & 7) * 8;
        if (r < 191) {
            const int rowabs = pb0 + r;
            cpa16(krsm + ((rowabs & 255) * FLH + c) * 2,
                  &g_kr[(((size_t)b * POS_ + rowabs) * NH_ + n) * DH_ + c]);
        }
    }
    cp_commit();

    // ---- build biased+scaled Q tile: (q + r_w_bias) * QSCALE ----
#pragma unroll
    for (int it = 0; it < 4; it++) {
        const int id = tid + it * 256;
        const int r = id >> 3, c = (id & 7) * 8;
        uint4 v = *(const uint4*)&g_qh[(((size_t)b * S_ + i0 + r) * NH_ + n) * DH_ + c];
        __nv_bfloat162* hp = (__nv_bfloat162*)&v;
        uint4 ow;
        uint32_t* wp = (uint32_t*)&ow;
#pragma unroll
        for (int k = 0; k < 4; k++) {
            float2 f = __bfloat1622float2(hp[k]);
            wp[k] = packbf((f.x + bw[c + 2 * k]) * QSCALE,
                           (f.y + bw[c + 2 * k + 1]) * QSCALE);
        }
        *(uint4*)&qw_s[r * FLH + c] = ow;
    }

    // ---- delta fragments: packed bf16 (br - bw)*QSCALE ----
    uint32_t dpk0[4], dpk1[4];
#pragma unroll
    for (int kc = 0; kc < 4; kc++) {
        const int kA = 16 * kc + 2 * tig;
        dpk0[kc] = packbf((br[kA] - bw[kA]) * QSCALE, (br[kA + 1] - bw[kA + 1]) * QSCALE);
        dpk1[kc] = packbf((br[kA + 8] - bw[kA + 8]) * QSCALE, (br[kA + 9] - bw[kA + 9]) * QSCALE);
    }
    __syncthreads();

    // ---- hoist ONLY the delta-added Qr fragments (afr); af reloaded per jt ----
    const uint32_t qwa = sptr(qw_s) + (((16 * w + (lane & 15)) * FLH + (lane >> 4) * 8) << 1);
    uint32_t afr[4][4];
#pragma unroll
    for (int kc = 0; kc < 4; kc++) {
        uint32_t aq[4];
        ldsm4(aq, qwa + kc * 32);
        __nv_bfloat162 r0 = __hadd2(*(__nv_bfloat162*)&aq[0], *(__nv_bfloat162*)&dpk0[kc]);
        __nv_bfloat162 r1 = __hadd2(*(__nv_bfloat162*)&aq[1], *(__nv_bfloat162*)&dpk0[kc]);
        __nv_bfloat162 r2 = __hadd2(*(__nv_bfloat162*)&aq[2], *(__nv_bfloat162*)&dpk1[kc]);
        __nv_bfloat162 r3 = __hadd2(*(__nv_bfloat162*)&aq[3], *(__nv_bfloat162*)&dpk1[kc]);
        afr[kc][0] = *(uint32_t*)&r0;
        afr[kc][1] = *(uint32_t*)&r1;
        afr[kc][2] = *(uint32_t*)&r2;
        afr[kc][3] = *(uint32_t*)&r3;
    }

    const uint32_t kvn = kvsm + (((((lane >> 4) * 8 + (lane & 7)) * FLH) + ((lane >> 3) & 1) * 8) << 1);
    const uint32_t kvt = kvsm + ((((lane & 15)) * FLH + (lane >> 4) * 8) << 1);
    const int laneRow = (lane >> 4) * 8 + (lane & 7);
    const int khalf   = ((lane >> 3) & 1) * 8;

    float l0v = 0.f, l1v = 0.f;
    float acc_o[8][4];
#pragma unroll
    for (int nt = 0; nt < 8; nt++)
#pragma unroll
        for (int e = 0; e < 4; e++) acc_o[nt][e] = 0.f;

    const int nt0 = 14 - 2 * w;
    float* gw = gsh + w * 16 * FGS;
    const int gi0 = i0 + 16 * w + g;
    const __nv_bfloat16* mrow0 = g_maskb + ((size_t)b * S_ + gi0) * S_;
    const __nv_bfloat16* mrow1 = mrow0 + 8 * S_;

    for (int jt = 0; jt < 16; jt++) {
        cp_wait0();
        __syncthreads();
        if (jt < 15) {
            const int j1 = (jt + 1) * 64;
            const uint32_t kvb = kvsm + (((jt + 1) & 1) * 64 * FLH << 1);
#pragma unroll
            for (int it = 0; it < 2; it++) {
                const int id = tid + it * 256;
                const int r = id >> 3, c = (id & 7) * 8;
                cpa16(kvb + (r * FLH + c) * 2,
                      &g_kvh[(((size_t)b * S_ + j1 + r) * NH_ + n) * DH_ + c]);
            }
            const int nb = pb0 + 64 * jt + 191;
#pragma unroll
            for (int it = 0; it < 2; it++) {
                const int id = tid + it * 256;
                const int r = id >> 3, c = (id & 7) * 8;
                const int rowabs = nb + r;
                cpa16(krsm + ((rowabs & 255) * FLH + c) * 2,
                      &g_kr[(((size_t)b * POS_ + rowabs) * NH_ + n) * DH_ + c]);
            }
            cp_commit();
        }
        const uint32_t kvo = ((jt & 1) * 64 * FLH) << 1;
        const int j0 = jt * 64;
        const int rowj = pb0 + 64 * jt + laneRow;

        // ---- S = Qw @ KV^T; af reloaded per kc (not held across jt) ----
        float acc_s[8][4];
#pragma unroll
        for (int nt = 0; nt < 8; nt++)
#pragma unroll
            for (int e = 0; e < 4; e++) acc_s[nt][e] = 0.f;
        {
            uint32_t sbf[2][4];
            ldsm4(sbf[0], kvn + kvo);
#pragma unroll
            for (int kc = 0; kc < 4; kc++) {
                uint32_t afk[4];
                ldsm4(afk, qwa + kc * 32);
#pragma unroll
                for (int nn = 0; nn < 4; nn++) {
                    const int it = kc * 4 + nn;
                    const int cur = it & 1;
                    if (it < 15) {
                        const int itn = it + 1;
                        const int kn = itn >> 2, nnn = itn & 3;
                        ldsm4(sbf[cur ^ 1], kvn + kvo + ((nnn * 16 * FLH + kn * 16) << 1));
                    }
                    mma16816(acc_s[2 * nn + 0], afk, &sbf[cur][0]);
                    mma16816(acc_s[2 * nn + 1], afk, &sbf[cur][2]);
                }
            }
        }

        // ---- banded G = Qr @ KR_ring^T, pipelined, scatter pre-shifted ----
        __syncwarp();
        {
            uint32_t gbf[2][4];
            {
                const int tr0 = nt0 * 8;
                ldsm4(gbf[0], krsm + ((((rowj + tr0) & 255) * FLH + khalf) << 1));
            }
#pragma unroll
            for (int np = 0; np < 5; np++) {
                const int tr = (nt0 + 2 * np) * 8;
                float ga[4] = {0.f, 0.f, 0.f, 0.f};
                float gb[4] = {0.f, 0.f, 0.f, 0.f};
#pragma unroll
                for (int kc = 0; kc < 4; kc++) {
                    const int it = np * 4 + kc;
                    const int cur = it & 1;
                    if (it < 19) {
                        const int itn = it + 1;
                        const int npn = itn >> 2, kn = itn & 3;
                        const int trn = (nt0 + 2 * npn) * 8;
                        ldsm4(gbf[cur ^ 1],
                              krsm + ((((rowj + trn) & 255) * FLH + khalf) << 1) + kn * 32);
                    }
                    mma16816(ga, afr[kc], &gbf[cur][0]);
                    mma16816(gb, afr[kc], &gbf[cur][2]);
                }
                const int base = tr + 2 * tig + 16 * w - 127;
                const int cA = base + g;
                const int cB = cA + 8;
                if ((unsigned)cA < 64u)        gw[g * FGS + cA]             = ga[0];
                if ((unsigned)(cA + 1) < 64u)  gw[g * FGS + cA + 1]         = ga[1];
                if ((unsigned)cB < 64u)        gw[(g + 8) * FGS + cB]       = ga[2];
                if ((unsigned)(cB + 1) < 64u)  gw[(g + 8) * FGS + cB + 1]   = ga[3];
                const int cA2 = cA + 8;
                const int cB2 = cB + 8;
                if ((unsigned)cA2 < 64u)       gw[g * FGS + cA2]            = gb[0];
                if ((unsigned)(cA2 + 1) < 64u) gw[g * FGS + cA2 + 1]        = gb[1];
                if ((unsigned)cB2 < 64u)       gw[(g + 8) * FGS + cB2]      = gb[2];
                if ((unsigned)(cB2 + 1) < 64u) gw[(g + 8) * FGS + cB2 + 1]  = gb[3];
            }
        }
        __syncwarp();

        // ---- static base-2 softmax: p = ex2(s + g + mask); l per-thread ----
        uint32_t pa[4][4];
#pragma unroll
        for (int nt = 0; nt < 8; nt++) {
            const int colb = nt * 8 + 2 * tig;
            const float2 mv0 = __bfloat1622float2(
                *(const __nv_bfloat162*)&mrow0[j0 + colb]);
            const float2 mv1 = __bfloat1622float2(
                *(const __nv_bfloat162*)&mrow1[j0 + colb]);
            const float2 gv0 = *(const float2*)&gw[g * FGS + colb];
            const float2 gv1 = *(const float2*)&gw[(g + 8) * FGS + colb];
            const float p0 = ex2f(acc_s[nt][0] + gv0.x + mv0.x);
            const float p1 = ex2f(acc_s[nt][1] + gv0.y + mv0.y);
            const float p2 = ex2f(acc_s[nt][2] + gv1.x + mv1.x);
            const float p3 = ex2f(acc_s[nt][3] + gv1.y + mv1.y);
            l0v += p0 + p1;
            l1v += p2 + p3;
            pa[nt >> 1][(nt & 1) * 2 + 0] = packbf(p0, p1);
            pa[nt >> 1][(nt & 1) * 2 + 1] = packbf(p2, p3);
        }

        // ---- O += P @ V, pipelined B fragments (no rescale needed) ----
        {
            uint32_t obf[2][4];
            ldsm4t(obf[0], kvt + kvo);
#pragma unroll
            for (int kc = 0; kc < 4; kc++) {
#pragma unroll
                for (int nn = 0; nn < 4; nn++) {
                    const int it = kc * 4 + nn;
                    const int cur = it & 1;
                    if (it < 15) {
                        const int itn = it + 1;
                        const int kn = itn >> 2, nnn = itn & 3;
                        ldsm4t(obf[cur ^ 1], kvt + kvo + ((kn * 16 * FLH + nnn * 16) << 1));
                    }
                    mma16816(acc_o[2 * nn + 0], pa[kc], &obf[cur][0]);
                    mma16816(acc_o[2 * nn + 1], pa[kc], &obf[cur][2]);
                }
            }
        }
    }

    // ---- one final l reduction across the quad, then normalize and store ----
    l0v += __shfl_xor_sync(0xffffffffu, l0v, 1);
    l0v += __shfl_xor_sync(0xffffffffu, l0v, 2);
    l1v += __shfl_xor_sync(0xffffffffu, l1v, 1);
    l1v += __shfl_xor_sync(0xffffffffu, l1v, 2);
    const float inv0 = 1.f / l0v, inv1 = 1.f / l1v;
    const size_t b0 = (((size_t)b * S_ + i0 + 16 * w + g) * NH_ + n) * (size_t)DH_;
    const size_t b1 = b0 + 8 * (size_t)NH_ * DH_;
#pragma unroll
    for (int nt = 0; nt < 8; nt++) {
        const int c = nt * 8 + 2 * tig;
        *(uint32_t*)&g_ctx[b0 + c] = packbf(acc_o[nt][0] * inv0, acc_o[nt][1] * inv0);
        *(uint32_t*)&g_ctx[b1 + c] = packbf(acc_o[nt][2] * inv1, acc_o[nt][3] * inv1);
    }
}

// -------------------------------- launch ---------------------------------------
extern "C" void kernel_launch(void* const* d_in, const int* in_sizes, int n_in,
                              void* d_out, int out_size)
{
    const float* hidden   = (const float*)d_in[0];
    const float* pos_emb  = (const float*)d_in[1];
    const float* mask     = (const float*)d_in[2];
    const float* qw       = (const float*)d_in[3];
    const float* kvw      = (const float*)d_in[4];
    const float* rw       = (const float*)d_in[5];
    const float* r_r_bias = (const float*)d_in[6];
    const float* r_w_bias = (const float*)d_in[7];
    const float* w_out    = (const float*)d_in[8];
    const float* b_out    = (const float*)d_in[9];
    float* out = (float*)d_out;

    const int gemm_smem  = 2 * QSTG * 2;                        // 53248 B
    const int flash_smem = (128 * FLH + 2 * 64 * FLH + 256 * FLH) * 2
                           + (8 * 16 * FGS + 128) * 4;          // 109056 B
    cudaFuncSetAttribute(proj_all,
                         cudaFuncAttributeMaxDynamicSharedMemorySize, gemm_smem);
    cudaFuncSetAttribute(gemm_epi,
                         cudaFuncAttributeMaxDynamicSharedMemorySize, gemm_smem);
    cudaFuncSetAttribute(flash_mma,
                         cudaFuncAttributeMaxDynamicSharedMemorySize, flash_smem);

    // fp32 -> bf16 conversion (inputs, weights, premultiplied mask)
    convert_all<<<2048, 256>>>(hidden, pos_emb, qw, kvw, rw, w_out, mask);

    // q + kv + r projections in a single launch (1536 CTAs of 64x128, occ 3)
    proj_all<<<1536, 256, gemm_smem>>>();

    // fused attention (static base-2 softmax, R13 configuration)
    flash_mma<<<dim3(S_/128, NH_, B_), 256, flash_smem>>>(r_w_bias, r_r_bias);

    // output projection + bias + residual + exact GELU (384 CTAs, occ 3)
    gemm_epi<<<384, 256, gemm_smem>>>(out, b_out, hidden);
}